// round 2
// baseline (speedup 1.0000x reference)
#include <cuda_runtime.h>
#include <math_constants.h>

#define BB     8
#define NN     4096
#define CIN    128
#define EOUT   5
#define SEMOUT 13
#define KSEL   30
#define QCAP   8
#define TP     32
#define XPAD   36
#define WPAD   129

#define FINF  __int_as_float(0x7f800000)
#define FNINF __int_as_float(0xff800000)

// ---------------- scratch (static __device__, no runtime alloc) ----------------
__device__ float  g_fsemT[BB * NN * CIN];   // 16MB  [b][n][c]
__device__ float4 g_t4[BB * NN];            // e0..e3
__device__ float2 g_t2[BB * NN];            // e4, r=||e||^2
__device__ int    g_nn[BB * NN * KSEL];     // neighbor indices

// ================================================================
// Phase 1: adapted = relu(gamma*(W_a@f_sem + b_a)+beta); y = f_ins + adapted;
//          e = W_ins@y + b_ins. Writes e_ins output, embedding table, f_sem^T.
// ================================================================
__global__ void __launch_bounds__(128, 2) phase1_kernel(
    const float* __restrict__ f_sem, const float* __restrict__ f_ins,
    const float* __restrict__ W_adapt, const float* __restrict__ b_adapt,
    const float* __restrict__ gamma, const float* __restrict__ beta,
    const float* __restrict__ W_ins, const float* __restrict__ b_ins,
    float* __restrict__ e_out)
{
    extern __shared__ float sm1[];
    float* Ws = sm1;                      // 128*129
    float* Xs = sm1 + 128 * WPAD;         // 128*36 (also reused as Ys)
    float* Wi = Xs + 128 * XPAD;          // 5*128 + 8

    const int tid = threadIdx.x;
    const int blk = blockIdx.x;
    const int b   = blk >> 7;             // 128 blocks per batch
    const int n0  = (blk & 127) * TP;

    // stage W_adapt (padded rows, conflict-free per-row access)
    for (int i = tid; i < 128 * 128; i += 128)
        Ws[(i >> 7) * WPAD + (i & 127)] = W_adapt[i];
    // stage W_ins + b_ins
    for (int i = tid; i < EOUT * 128; i += 128) Wi[i] = W_ins[i];
    if (tid < EOUT) Wi[EOUT * 128 + tid] = b_ins[tid];

    // stage X tile [128 ch][32 pts], coalesced
    const float* fs = f_sem + ((size_t)b * CIN) * NN + n0;
    for (int i = tid; i < 128 * TP; i += 128) {
        int c = i >> 5, p = i & 31;
        Xs[c * XPAD + p] = fs[(size_t)c * NN + p];
    }
    __syncthreads();

    // transpose-write f_sem^T (coalesced stores: lanes = consecutive channels)
    {
        float* dst = g_fsemT + ((size_t)(b * NN + n0)) * CIN + tid;
        #pragma unroll 4
        for (int p = 0; p < TP; p++)
            dst[(size_t)p * CIN] = Xs[tid * XPAD + p];
    }

    // GEMM: thread = output channel o, 32 points in registers
    float acc[TP];
    #pragma unroll
    for (int p = 0; p < TP; p++) acc[p] = 0.f;
    const float* wrow = Ws + tid * WPAD;
    #pragma unroll 2
    for (int c = 0; c < 128; c++) {
        float w = wrow[c];
        const float4* xr = (const float4*)(Xs + c * XPAD);
        #pragma unroll
        for (int p4 = 0; p4 < TP / 4; p4++) {
            float4 x = xr[p4];
            acc[4 * p4 + 0] = fmaf(w, x.x, acc[4 * p4 + 0]);
            acc[4 * p4 + 1] = fmaf(w, x.y, acc[4 * p4 + 1]);
            acc[4 * p4 + 2] = fmaf(w, x.z, acc[4 * p4 + 2]);
            acc[4 * p4 + 3] = fmaf(w, x.w, acc[4 * p4 + 3]);
        }
    }

    // epilogue: BN(eval) + ReLU + residual
    const float g  = gamma[tid];
    const float bb = fmaf(g, b_adapt[tid], beta[tid]);
    const float* fi = f_ins + ((size_t)(b * CIN + tid)) * NN + n0;
    float y[TP];
    #pragma unroll
    for (int p = 0; p < TP; p++) {
        float a = fmaxf(fmaf(g, acc[p], bb), 0.f);
        y[p] = fi[p] + a;
    }
    __syncthreads();                      // Xs fully consumed
    #pragma unroll
    for (int p = 0; p < TP; p++) Xs[tid * XPAD + p] = y[p];
    __syncthreads();

    // second conv (5 x 128), one warp
    if (tid < TP) {
        const int p = tid;
        float e[EOUT];
        #pragma unroll
        for (int j = 0; j < EOUT; j++) e[j] = Wi[EOUT * 128 + j];
        #pragma unroll 4
        for (int c = 0; c < 128; c++) {
            float x = Xs[c * XPAD + p];
            #pragma unroll
            for (int j = 0; j < EOUT; j++) e[j] = fmaf(Wi[j * 128 + c], x, e[j]);
        }
        float r = 0.f;
        #pragma unroll
        for (int j = 0; j < EOUT; j++) r = fmaf(e[j], e[j], r);
        const int n = n0 + p;
        float* eo = e_out + (size_t)b * EOUT * NN + n;
        #pragma unroll
        for (int j = 0; j < EOUT; j++) eo[(size_t)j * NN] = e[j];
        g_t4[b * NN + n] = make_float4(e[0], e[1], e[2], e[3]);
        g_t2[b * NN + n] = make_float2(e[4], r);
    }
}

// ================================================================
// Phase 2: exact K=30 NN per query. Thread-per-query, smem table,
// per-lane staging queue + warp-ballot batched heap flush.
// ================================================================
__device__ __forceinline__ void heap_insert(float* hd, int* hi, float s, int id)
{
    // hd/hi already offset by tid; slot stride 256
    if (s >= hd[0]) return;
    int pos = 0;
    while (true) {
        int l = 2 * pos + 1, r = l + 1;
        float lv = (l < KSEL) ? hd[l * 256] : FNINF;
        float rv = (r < KSEL) ? hd[r * 256] : FNINF;
        int   ch; float cv;
        if (lv >= rv) { ch = l; cv = lv; } else { ch = r; cv = rv; }
        if (cv <= s) break;
        hd[pos * 256] = cv; hi[pos * 256] = hi[ch * 256];
        pos = ch;
    }
    hd[pos * 256] = s; hi[pos * 256] = id;
}

__global__ void __launch_bounds__(256, 1) knn_kernel()
{
    extern __shared__ float sm2[];
    float4* st4 = (float4*)sm2;                       // 4096 * 16B
    float2* st2 = (float2*)(st4 + NN);                // 4096 * 8B
    float*  qs  = (float*)(st2 + NN);                 // QCAP*256
    int*    qi  = (int*)(qs + QCAP * 256);            // QCAP*256
    float*  hd  = (float*)(qi + QCAP * 256);          // KSEL*256
    int*    hi  = (int*)(hd + KSEL * 256);            // KSEL*256

    const int tid = threadIdx.x;
    const int b   = blockIdx.x >> 4;                  // 16 blocks / batch
    const int q   = ((blockIdx.x & 15) << 8) + tid;

    for (int i = tid; i < NN; i += 256) {
        st4[i] = g_t4[b * NN + i];
        st2[i] = g_t2[b * NN + i];
    }
    #pragma unroll
    for (int j = 0; j < KSEL; j++) hd[j * 256 + tid] = FINF;
    __syncthreads();

    const float4 Q  = st4[q];
    const float  q4 = st2[q].x;
    float* myhd = hd + tid; int* myhi = hi + tid;
    float* myqs = qs + tid; int* myqi = qi + tid;
    float tau = FINF;
    int   cnt = 0;

    #pragma unroll 4
    for (int m = 0; m < NN; m++) {
        float4 t = st4[m];
        float2 u = st2[m];
        float d = t.x * Q.x;
        d = fmaf(t.y, Q.y, d);
        d = fmaf(t.z, Q.z, d);
        d = fmaf(t.w, Q.w, d);
        d = fmaf(u.x, q4, d);
        float s = fmaf(-2.f, d, u.y);      // r[m] - 2*dot  (== dist up to +const)
        if (s < tau) { myqs[cnt * 256] = s; myqi[cnt * 256] = m; cnt++; }
        if (__any_sync(0xffffffffu, cnt == QCAP)) {
            for (int j = 0; j < cnt; j++)
                heap_insert(myhd, myhi, myqs[j * 256], myqi[j * 256]);
            cnt = 0;
            tau = myhd[0];
        }
    }
    for (int j = 0; j < cnt; j++)
        heap_insert(myhd, myhi, myqs[j * 256], myqi[j * 256]);

    int* dst = g_nn + ((size_t)(b * NN + q)) * KSEL;
    #pragma unroll
    for (int j = 0; j < KSEL; j++) dst[j] = myhi[j * 256];
}

// ================================================================
// Phase 3: warp-per-query gather-max over 30 neighbors (128 ch) + 13x128 conv
// ================================================================
__global__ void __launch_bounds__(256) gather_kernel(
    const float* __restrict__ W_sem, const float* __restrict__ b_sem,
    float* __restrict__ p_out)
{
    const int warp = (blockIdx.x << 3) + (threadIdx.x >> 5);
    const int lane = threadIdx.x & 31;
    const int b = warp >> 12, n = warp & (NN - 1);

    const int* nnp = g_nn + (size_t)warp * KSEL;
    int myid = nnp[lane < KSEL ? lane : 0];

    const float* base = g_fsemT + ((size_t)b * NN) * CIN + (lane << 2);
    float4 vmax = make_float4(FNINF, FNINF, FNINF, FNINF);
    #pragma unroll 6
    for (int k = 0; k < KSEL; k++) {
        int j = __shfl_sync(0xffffffffu, myid, k);
        float4 v = *(const float4*)(base + (size_t)j * CIN);
        vmax.x = fmaxf(vmax.x, v.x);
        vmax.y = fmaxf(vmax.y, v.y);
        vmax.z = fmaxf(vmax.z, v.z);
        vmax.w = fmaxf(vmax.w, v.w);
    }

    float out[SEMOUT];
    #pragma unroll
    for (int o = 0; o < SEMOUT; o++) {
        float4 w = *(const float4*)(W_sem + o * CIN + (lane << 2));
        float a = w.x * vmax.x;
        a = fmaf(w.y, vmax.y, a);
        a = fmaf(w.z, vmax.z, a);
        a = fmaf(w.w, vmax.w, a);
        a += __shfl_xor_sync(0xffffffffu, a, 16);
        a += __shfl_xor_sync(0xffffffffu, a, 8);
        a += __shfl_xor_sync(0xffffffffu, a, 4);
        a += __shfl_xor_sync(0xffffffffu, a, 2);
        a += __shfl_xor_sync(0xffffffffu, a, 1);
        out[o] = a;
    }
    if (lane == 0) {
        float* dst = p_out + ((size_t)b * SEMOUT) * NN + n;
        #pragma unroll
        for (int o = 0; o < SEMOUT; o++)
            dst[(size_t)o * NN] = out[o] + b_sem[o];
    }
}

// ================================================================
extern "C" void kernel_launch(void* const* d_in, const int* in_sizes, int n_in,
                              void* d_out, int out_size)
{
    (void)in_sizes; (void)n_in; (void)out_size;
    const float* f_sem   = (const float*)d_in[0];
    const float* f_ins   = (const float*)d_in[1];
    const float* W_adapt = (const float*)d_in[2];
    const float* b_adapt = (const float*)d_in[3];
    const float* gamma   = (const float*)d_in[4];
    const float* beta    = (const float*)d_in[5];
    const float* W_ins   = (const float*)d_in[6];
    const float* b_ins   = (const float*)d_in[7];
    const float* W_sem   = (const float*)d_in[8];
    const float* b_sem   = (const float*)d_in[9];

    float* p_out = (float*)d_out;                       // [B,13,N] first
    float* e_out = p_out + (size_t)BB * SEMOUT * NN;    // [B,5,N] second

    const int smem1 = (128 * WPAD + 128 * XPAD + EOUT * 128 + 8) * 4;
    const int smem2 = NN * 16 + NN * 8 + QCAP * 256 * 8 + KSEL * 256 * 8;

    cudaFuncSetAttribute(phase1_kernel, cudaFuncAttributeMaxDynamicSharedMemorySize, smem1);
    cudaFuncSetAttribute(knn_kernel,    cudaFuncAttributeMaxDynamicSharedMemorySize, smem2);

    phase1_kernel<<<BB * (NN / TP), 128, smem1>>>(
        f_sem, f_ins, W_adapt, b_adapt, gamma, beta, W_ins, b_ins, e_out);
    knn_kernel<<<BB * (NN / 256), 256, smem2>>>();
    gather_kernel<<<(BB * NN) / 8, 256>>>(W_sem, b_sem, p_out);
}

// round 4
// speedup vs baseline: 1.0813x; 1.0813x over previous
#include <cuda_runtime.h>
#include <math_constants.h>

#define BB     8
#define NN     4096
#define CIN    128
#define EOUT   5
#define SEMOUT 13
#define KSEL   30
#define QCAP   8
#define TP     32
#define XPAD   36
#define WPAD   129

#define FINF  __int_as_float(0x7f800000)
#define FNINF __int_as_float(0xff800000)

// ---------------- scratch (static __device__, no runtime alloc) ----------------
__device__ float  g_fsemT[BB * NN * CIN];   // 16MB  [b][n][c]
__device__ float4 g_t4[BB * NN];            // e0..e3
__device__ float2 g_t2[BB * NN];            // e4, r=||e||^2
__device__ int    g_nn[BB * NN * KSEL];     // neighbor indices

// ================================================================
// Phase 1 (R1 logic; only change: W_adapt staged in 4 chunks of 32 cin
// columns -> smem 42KB -> 4-5 blocks/SM instead of 2).
// ================================================================
__global__ void __launch_bounds__(128, 4) phase1_kernel(
    const float* __restrict__ f_sem, const float* __restrict__ f_ins,
    const float* __restrict__ W_adapt, const float* __restrict__ b_adapt,
    const float* __restrict__ gamma, const float* __restrict__ beta,
    const float* __restrict__ W_ins, const float* __restrict__ b_ins,
    float* __restrict__ e_out)
{
    extern __shared__ float sm1[];
    float* Ws = sm1;                      // 32*129 = 4128 floats (one chunk)
    float* Xs = sm1 + 32 * WPAD;          // 128*36 (reused as Ys)
    float* Wi = Xs + 128 * XPAD;          // 5*128 + 8

    const int tid = threadIdx.x;
    const int blk = blockIdx.x;
    const int b   = blk >> 7;             // 128 blocks per batch
    const int n0  = (blk & 127) * TP;

    // stage W_ins + b_ins
    for (int i = tid; i < EOUT * 128; i += 128) Wi[i] = W_ins[i];
    if (tid < EOUT) Wi[EOUT * 128 + tid] = b_ins[tid];

    // stage X tile [128 ch][32 pts], coalesced (R1)
    const float* fs = f_sem + ((size_t)b * CIN) * NN + n0;
    for (int i = tid; i < 128 * TP; i += 128) {
        int c = i >> 5, p = i & 31;
        Xs[c * XPAD + p] = fs[(size_t)c * NN + p];
    }
    __syncthreads();

    // transpose-write f_sem^T (R1: coalesced STG, bank-conflicted LDS — proven)
    {
        float* dst = g_fsemT + ((size_t)(b * NN + n0)) * CIN + tid;
        #pragma unroll 4
        for (int p = 0; p < TP; p++)
            dst[(size_t)p * CIN] = Xs[tid * XPAD + p];
    }

    // GEMM: thread = output channel tid, 32 points in registers (scalar fmaf, R1 math)
    float acc[TP];
    #pragma unroll
    for (int p = 0; p < TP; p++) acc[p] = 0.f;

    #pragma unroll 1
    for (int ch = 0; ch < 4; ch++) {
        if (ch) __syncthreads();
        // stage chunk: Ws[cc*129 + o] = W_adapt[o][ch*32 + cc]; coalesced LDG
        for (int i = tid; i < 32 * 128; i += 128) {
            int o  = i >> 5;
            int cc = i & 31;
            Ws[cc * WPAD + o] = W_adapt[o * 128 + ch * 32 + cc];
        }
        __syncthreads();

        #pragma unroll 4
        for (int cc = 0; cc < 32; cc++) {
            float w = Ws[cc * WPAD + tid];
            const float4* xr = (const float4*)(Xs + (ch * 32 + cc) * XPAD);
            #pragma unroll
            for (int p4 = 0; p4 < TP / 4; p4++) {
                float4 x = xr[p4];
                acc[4 * p4 + 0] = fmaf(w, x.x, acc[4 * p4 + 0]);
                acc[4 * p4 + 1] = fmaf(w, x.y, acc[4 * p4 + 1]);
                acc[4 * p4 + 2] = fmaf(w, x.z, acc[4 * p4 + 2]);
                acc[4 * p4 + 3] = fmaf(w, x.w, acc[4 * p4 + 3]);
            }
        }
    }

    // epilogue: BN(eval) + ReLU + residual (R1)
    const float g  = gamma[tid];
    const float bb = fmaf(g, b_adapt[tid], beta[tid]);
    const float* fi = f_ins + ((size_t)(b * CIN + tid)) * NN + n0;
    float y[TP];
    #pragma unroll
    for (int p = 0; p < TP; p++) {
        float a = fmaxf(fmaf(g, acc[p], bb), 0.f);
        y[p] = fi[p] + a;
    }
    __syncthreads();                      // Xs fully consumed
    #pragma unroll
    for (int p = 0; p < TP; p++) Xs[tid * XPAD + p] = y[p];
    __syncthreads();

    // second conv (5 x 128), one warp (R1)
    if (tid < TP) {
        const int p = tid;
        float e[EOUT];
        #pragma unroll
        for (int j = 0; j < EOUT; j++) e[j] = Wi[EOUT * 128 + j];
        #pragma unroll 4
        for (int c = 0; c < 128; c++) {
            float x = Xs[c * XPAD + p];
            #pragma unroll
            for (int j = 0; j < EOUT; j++) e[j] = fmaf(Wi[j * 128 + c], x, e[j]);
        }
        float r = 0.f;
        #pragma unroll
        for (int j = 0; j < EOUT; j++) r = fmaf(e[j], e[j], r);
        const int n = n0 + p;
        float* eo = e_out + (size_t)b * EOUT * NN + n;
        #pragma unroll
        for (int j = 0; j < EOUT; j++) eo[(size_t)j * NN] = e[j];
        g_t4[b * NN + n] = make_float4(e[0], e[1], e[2], e[3]);
        g_t2[b * NN + n] = make_float2(e[4], r);
    }
}

// ================================================================
// Phase 2: exact K=30 NN (R1 logic + heap prefill with first 30 candidates).
// Max-heap of kept distances; keep 30 smallest s = r - 2*dot.
// ================================================================
__device__ __forceinline__ void sift_max(float* hd, int* hi, int pos, float s, int id)
{
    // hd/hi already offset by tid; slot stride 256. Same body as R1 heap_insert.
    while (true) {
        int l = 2 * pos + 1, r = l + 1;
        float lv = (l < KSEL) ? hd[l * 256] : FNINF;
        float rv = (r < KSEL) ? hd[r * 256] : FNINF;
        int   ch; float cv;
        if (lv >= rv) { ch = l; cv = lv; } else { ch = r; cv = rv; }
        if (cv <= s) break;
        hd[pos * 256] = cv; hi[pos * 256] = hi[ch * 256];
        pos = ch;
    }
    hd[pos * 256] = s; hi[pos * 256] = id;
}

__device__ __forceinline__ float cand_score(
    const float4* __restrict__ st4, const float2* __restrict__ st2,
    int m, float4 Q, float q4)
{
    float4 t = st4[m];
    float2 u = st2[m];
    float d = t.x * Q.x;
    d = fmaf(t.y, Q.y, d);
    d = fmaf(t.z, Q.z, d);
    d = fmaf(t.w, Q.w, d);
    d = fmaf(u.x, q4, d);
    return fmaf(-2.f, d, u.y);            // r[m] - 2*dot (== dist up to +const)
}

__global__ void __launch_bounds__(256, 1) knn_kernel()
{
    extern __shared__ float sm2[];
    float4* st4 = (float4*)sm2;                       // 4096 * 16B
    float2* st2 = (float2*)(st4 + NN);                // 4096 * 8B
    float*  qs  = (float*)(st2 + NN);                 // QCAP*256
    int*    qi  = (int*)(qs + QCAP * 256);            // QCAP*256
    float*  hd  = (float*)(qi + QCAP * 256);          // KSEL*256
    int*    hi  = (int*)(hd + KSEL * 256);            // KSEL*256

    const int tid = threadIdx.x;
    const int b   = blockIdx.x >> 4;                  // 16 blocks / batch
    const int q   = ((blockIdx.x & 15) << 8) + tid;

    for (int i = tid; i < NN; i += 256) {
        st4[i] = g_t4[b * NN + i];
        st2[i] = g_t2[b * NN + i];
    }
    __syncthreads();

    const float4 Q  = st4[q];
    const float  q4 = st2[q].x;
    float* myhd = hd + tid; int* myhi = hi + tid;
    float* myqs = qs + tid; int* myqi = qi + tid;

    // prefill heap with candidates 0..29, then heapify (max-heap of kept dists)
    #pragma unroll
    for (int m = 0; m < KSEL; m++) {
        myhd[m * 256] = cand_score(st4, st2, m, Q, q4);
        myhi[m * 256] = m;
    }
    #pragma unroll
    for (int i = KSEL / 2 - 1; i >= 0; i--)
        sift_max(myhd, myhi, i, myhd[i * 256], myhi[i * 256]);

    float tau = myhd[0];
    int   cnt = 0;

    #pragma unroll 4
    for (int m = KSEL; m < NN; m++) {
        float s = cand_score(st4, st2, m, Q, q4);
        if (s < tau) { myqs[cnt * 256] = s; myqi[cnt * 256] = m; cnt++; }
        if (__any_sync(0xffffffffu, cnt == QCAP)) {
            for (int j = 0; j < cnt; j++) {
                float v = myqs[j * 256];
                if (v < myhd[0]) sift_max(myhd, myhi, 0, v, myqi[j * 256]);
            }
            cnt = 0;
            tau = myhd[0];
        }
    }
    for (int j = 0; j < cnt; j++) {
        float v = myqs[j * 256];
        if (v < myhd[0]) sift_max(myhd, myhi, 0, v, myqi[j * 256]);
    }

    int* dst = g_nn + ((size_t)(b * NN + q)) * KSEL;
    #pragma unroll
    for (int j = 0; j < KSEL; j++) dst[j] = myhi[j * 256];
}

// ================================================================
// Phase 3: warp-per-query gather-max over 30 neighbors (128 ch) + 13x128 conv
// ================================================================
__global__ void __launch_bounds__(256) gather_kernel(
    const float* __restrict__ W_sem, const float* __restrict__ b_sem,
    float* __restrict__ p_out)
{
    const int warp = (blockIdx.x << 3) + (threadIdx.x >> 5);
    const int lane = threadIdx.x & 31;
    const int b = warp >> 12, n = warp & (NN - 1);

    const int* nnp = g_nn + (size_t)warp * KSEL;
    int myid = nnp[lane < KSEL ? lane : 0];

    const float* base = g_fsemT + ((size_t)b * NN) * CIN + (lane << 2);
    float4 vmax = make_float4(FNINF, FNINF, FNINF, FNINF);
    #pragma unroll 6
    for (int k = 0; k < KSEL; k++) {
        int j = __shfl_sync(0xffffffffu, myid, k);
        float4 v = *(const float4*)(base + (size_t)j * CIN);
        vmax.x = fmaxf(vmax.x, v.x);
        vmax.y = fmaxf(vmax.y, v.y);
        vmax.z = fmaxf(vmax.z, v.z);
        vmax.w = fmaxf(vmax.w, v.w);
    }

    float out[SEMOUT];
    #pragma unroll
    for (int o = 0; o < SEMOUT; o++) {
        float4 w = *(const float4*)(W_sem + o * CIN + (lane << 2));
        float a = w.x * vmax.x;
        a = fmaf(w.y, vmax.y, a);
        a = fmaf(w.z, vmax.z, a);
        a = fmaf(w.w, vmax.w, a);
        a += __shfl_xor_sync(0xffffffffu, a, 16);
        a += __shfl_xor_sync(0xffffffffu, a, 8);
        a += __shfl_xor_sync(0xffffffffu, a, 4);
        a += __shfl_xor_sync(0xffffffffu, a, 2);
        a += __shfl_xor_sync(0xffffffffu, a, 1);
        out[o] = a;
    }
    if (lane == 0) {
        float* dst = p_out + ((size_t)b * SEMOUT) * NN + n;
        #pragma unroll
        for (int o = 0; o < SEMOUT; o++)
            dst[(size_t)o * NN] = out[o] + b_sem[o];
    }
}

// ================================================================
extern "C" void kernel_launch(void* const* d_in, const int* in_sizes, int n_in,
                              void* d_out, int out_size)
{
    (void)in_sizes; (void)n_in; (void)out_size;
    const float* f_sem   = (const float*)d_in[0];
    const float* f_ins   = (const float*)d_in[1];
    const float* W_adapt = (const float*)d_in[2];
    const float* b_adapt = (const float*)d_in[3];
    const float* gamma   = (const float*)d_in[4];
    const float* beta    = (const float*)d_in[5];
    const float* W_ins   = (const float*)d_in[6];
    const float* b_ins   = (const float*)d_in[7];
    const float* W_sem   = (const float*)d_in[8];
    const float* b_sem   = (const float*)d_in[9];

    float* p_out = (float*)d_out;                       // [B,13,N] first
    float* e_out = p_out + (size_t)BB * SEMOUT * NN;    // [B,5,N] second

    const int smem1 = (32 * WPAD + 128 * XPAD + EOUT * 128 + 8) * 4;
    const int smem2 = NN * 16 + NN * 8 + QCAP * 256 * 8 + KSEL * 256 * 8;

    cudaFuncSetAttribute(phase1_kernel, cudaFuncAttributeMaxDynamicSharedMemorySize, smem1);
    cudaFuncSetAttribute(knn_kernel,    cudaFuncAttributeMaxDynamicSharedMemorySize, smem2);

    phase1_kernel<<<BB * (NN / TP), 128, smem1>>>(
        f_sem, f_ins, W_adapt, b_adapt, gamma, beta, W_ins, b_ins, e_out);
    knn_kernel<<<BB * (NN / 256), 256, smem2>>>();
    gather_kernel<<<(BB * NN) / 8, 256>>>(W_sem, b_sem, p_out);
}

// round 5
// speedup vs baseline: 1.3424x; 1.2415x over previous
#include <cuda_runtime.h>
#include <math_constants.h>

#define BB     8
#define NN     4096
#define CIN    128
#define EOUT   5
#define SEMOUT 13
#define KSEL   30
#define QCAP   16
#define TP     32
#define XPAD   36
#define WPAD   129
#define NSLICE 2
#define SLEN   (NN / NSLICE)
#define KQT    128            // queries (threads) per knn block

#define FINF  __int_as_float(0x7f800000)
#define FNINF __int_as_float(0xff800000)

struct Tab { float4 a; float4 b; };   // a = e0..e3, b = (e4, r=||e||^2, 0, 0)

// ---------------- scratch (static __device__, no runtime alloc) ----------------
__device__ float g_fsemT[BB * NN * CIN];            // 16MB [b][n][c]
__device__ Tab   g_tab[BB * NN];                    // 1MB embedding table
__device__ int   g_nn[BB * NN * KSEL];              // final neighbor indices
__device__ float g_pd[BB * NN * NSLICE * KSEL];     // partial scores
__device__ int   g_pi[BB * NN * NSLICE * KSEL];     // partial indices

// ================================================================
// Phase 1 (identical to R3 except table write goes to g_tab)
// ================================================================
__global__ void __launch_bounds__(128, 4) phase1_kernel(
    const float* __restrict__ f_sem, const float* __restrict__ f_ins,
    const float* __restrict__ W_adapt, const float* __restrict__ b_adapt,
    const float* __restrict__ gamma, const float* __restrict__ beta,
    const float* __restrict__ W_ins, const float* __restrict__ b_ins,
    float* __restrict__ e_out)
{
    extern __shared__ float sm1[];
    float* Ws = sm1;                      // 32*129 (one W chunk)
    float* Xs = sm1 + 32 * WPAD;          // 128*36 (reused as Ys)
    float* Wi = Xs + 128 * XPAD;          // 5*128 + 8

    const int tid = threadIdx.x;
    const int blk = blockIdx.x;
    const int b   = blk >> 7;
    const int n0  = (blk & 127) * TP;

    for (int i = tid; i < EOUT * 128; i += 128) Wi[i] = W_ins[i];
    if (tid < EOUT) Wi[EOUT * 128 + tid] = b_ins[tid];

    const float* fs = f_sem + ((size_t)b * CIN) * NN + n0;
    for (int i = tid; i < 128 * TP; i += 128) {
        int c = i >> 5, p = i & 31;
        Xs[c * XPAD + p] = fs[(size_t)c * NN + p];
    }
    __syncthreads();

    {
        float* dst = g_fsemT + ((size_t)(b * NN + n0)) * CIN + tid;
        #pragma unroll 4
        for (int p = 0; p < TP; p++)
            dst[(size_t)p * CIN] = Xs[tid * XPAD + p];
    }

    float acc[TP];
    #pragma unroll
    for (int p = 0; p < TP; p++) acc[p] = 0.f;

    #pragma unroll 1
    for (int ch = 0; ch < 4; ch++) {
        if (ch) __syncthreads();
        for (int i = tid; i < 32 * 128; i += 128) {
            int o  = i >> 5;
            int cc = i & 31;
            Ws[cc * WPAD + o] = W_adapt[o * 128 + ch * 32 + cc];
        }
        __syncthreads();

        #pragma unroll 4
        for (int cc = 0; cc < 32; cc++) {
            float w = Ws[cc * WPAD + tid];
            const float4* xr = (const float4*)(Xs + (ch * 32 + cc) * XPAD);
            #pragma unroll
            for (int p4 = 0; p4 < TP / 4; p4++) {
                float4 x = xr[p4];
                acc[4 * p4 + 0] = fmaf(w, x.x, acc[4 * p4 + 0]);
                acc[4 * p4 + 1] = fmaf(w, x.y, acc[4 * p4 + 1]);
                acc[4 * p4 + 2] = fmaf(w, x.z, acc[4 * p4 + 2]);
                acc[4 * p4 + 3] = fmaf(w, x.w, acc[4 * p4 + 3]);
            }
        }
    }

    const float g  = gamma[tid];
    const float bb = fmaf(g, b_adapt[tid], beta[tid]);
    const float* fi = f_ins + ((size_t)(b * CIN + tid)) * NN + n0;
    float y[TP];
    #pragma unroll
    for (int p = 0; p < TP; p++) {
        float a = fmaxf(fmaf(g, acc[p], bb), 0.f);
        y[p] = fi[p] + a;
    }
    __syncthreads();
    #pragma unroll
    for (int p = 0; p < TP; p++) Xs[tid * XPAD + p] = y[p];
    __syncthreads();

    if (tid < TP) {
        const int p = tid;
        float e[EOUT];
        #pragma unroll
        for (int j = 0; j < EOUT; j++) e[j] = Wi[EOUT * 128 + j];
        #pragma unroll 4
        for (int c = 0; c < 128; c++) {
            float x = Xs[c * XPAD + p];
            #pragma unroll
            for (int j = 0; j < EOUT; j++) e[j] = fmaf(Wi[j * 128 + c], x, e[j]);
        }
        float r = 0.f;
        #pragma unroll
        for (int j = 0; j < EOUT; j++) r = fmaf(e[j], e[j], r);
        const int n = n0 + p;
        float* eo = e_out + (size_t)b * EOUT * NN + n;
        #pragma unroll
        for (int j = 0; j < EOUT; j++) eo[(size_t)j * NN] = e[j];
        Tab t;
        t.a = make_float4(e[0], e[1], e[2], e[3]);
        t.b = make_float4(e[4], r, 0.f, 0.f);
        g_tab[b * NN + n] = t;
    }
}

// ================================================================
// Phase 2a: partial K=30 NN over one candidate slice (2048).
// 128 query-threads/block, candidates read via warp-uniform LDG.
// ================================================================
__device__ __forceinline__ void sift_max(float* hd, int* hi, int pos, float s, int id)
{
    while (true) {
        int l = 2 * pos + 1, r = l + 1;
        float lv = (l < KSEL) ? hd[l * KQT] : FNINF;
        float rv = (r < KSEL) ? hd[r * KQT] : FNINF;
        int   ch; float cv;
        if (lv >= rv) { ch = l; cv = lv; } else { ch = r; cv = rv; }
        if (cv <= s) break;
        hd[pos * KQT] = cv; hi[pos * KQT] = hi[ch * KQT];
        pos = ch;
    }
    hd[pos * KQT] = s; hi[pos * KQT] = id;
}

__device__ __forceinline__ float tab_score(const Tab* __restrict__ tab, int m,
                                           float4 Q, float q4)
{
    float4 ta = __ldg(&tab[m].a);
    float4 tb = __ldg(&tab[m].b);
    float d = ta.x * Q.x;
    d = fmaf(ta.y, Q.y, d);
    d = fmaf(ta.z, Q.z, d);
    d = fmaf(ta.w, Q.w, d);
    d = fmaf(tb.x, q4, d);
    return fmaf(-2.f, d, tb.y);           // r[m] - 2*dot (dist up to +const)
}

__global__ void __launch_bounds__(KQT, 4) knn_partial_kernel()
{
    __shared__ float hd[KSEL * KQT];
    __shared__ int   hi[KSEL * KQT];
    __shared__ float qs[QCAP * KQT];
    __shared__ int   qi[QCAP * KQT];

    const int tid  = threadIdx.x;
    const int b    = blockIdx.x >> 6;             // 64 blocks per batch
    const int qblk = (blockIdx.x >> 1) & 31;
    const int sl   = blockIdx.x & 1;
    const int q    = (qblk << 7) + tid;
    const int base = sl * SLEN;

    const Tab* tab = g_tab + b * NN;
    const float4 Qa = __ldg(&tab[q].a);
    const float  q4 = __ldg(&tab[q].b).x;

    float* myhd = hd + tid; int* myhi = hi + tid;
    float* myqs = qs + tid; int* myqi = qi + tid;

    // prefill with first 30 candidates of slice, heapify (max-heap of kept)
    #pragma unroll
    for (int j = 0; j < KSEL; j++) {
        myhd[j * KQT] = tab_score(tab, base + j, Qa, q4);
        myhi[j * KQT] = base + j;
    }
    #pragma unroll
    for (int i = KSEL / 2 - 1; i >= 0; i--)
        sift_max(myhd, myhi, i, myhd[i * KQT], myhi[i * KQT]);

    float tau = myhd[0];
    int   cnt = 0;
    int   m   = base + KSEL;
    const int mend8 = base + KSEL + ((SLEN - KSEL) & ~7);

    #pragma unroll 1
    for (; m < mend8; m += 8) {
        #pragma unroll
        for (int uu = 0; uu < 8; uu++) {
            float s = tab_score(tab, m + uu, Qa, q4);
            if (s < tau) { myqs[cnt * KQT] = s; myqi[cnt * KQT] = m + uu; cnt++; }
        }
        if (__any_sync(0xffffffffu, cnt > 8)) {
            for (int j = 0; j < cnt; j++) {
                float v = myqs[j * KQT];
                if (v < myhd[0]) sift_max(myhd, myhi, 0, v, myqi[j * KQT]);
            }
            cnt = 0;
            tau = myhd[0];
        }
    }
    for (; m < base + SLEN; m++) {
        float s = tab_score(tab, m, Qa, q4);
        if (s < tau) { myqs[cnt * KQT] = s; myqi[cnt * KQT] = m; cnt++; }
    }
    for (int j = 0; j < cnt; j++) {
        float v = myqs[j * KQT];
        if (v < myhd[0]) sift_max(myhd, myhi, 0, v, myqi[j * KQT]);
    }

    // emit partial list (unordered 30)
    const size_t off = ((size_t)(b * NN + q) * NSLICE + sl) * KSEL;
    #pragma unroll
    for (int j = 0; j < KSEL; j++) {
        g_pd[off + j] = myhd[j * KQT];
        g_pi[off + j] = myhi[j * KQT];
    }
}

// ================================================================
// Phase 2b: merge NSLICE*30 partials -> 30 smallest. Warp per query,
// rank selection with (score, idx) lexicographic order (ranks unique).
// ================================================================
__global__ void __launch_bounds__(256) knn_merge_kernel()
{
    const int wq   = (blockIdx.x << 3) + (threadIdx.x >> 5);  // query id 0..BB*NN-1
    const int lane = threadIdx.x & 31;

    const size_t off = (size_t)wq * (NSLICE * KSEL);
    float s0 = FINF, s1 = FINF;
    int   i0 = 0x7fffffff, i1 = 0x7fffffff;
    if (lane < KSEL) {
        s0 = g_pd[off + lane];         i0 = g_pi[off + lane];
        s1 = g_pd[off + KSEL + lane];  i1 = g_pi[off + KSEL + lane];
    }

    int r0 = 0, r1 = 0;
    #pragma unroll
    for (int j = 0; j < KSEL; j++) {
        float a  = __shfl_sync(0xffffffffu, s0, j);
        int   ai = __shfl_sync(0xffffffffu, i0, j);
        r0 += (a < s0) || (a == s0 && ai < i0);
        r1 += (a < s1) || (a == s1 && ai < i1);
        float c  = __shfl_sync(0xffffffffu, s1, j);
        int   ci = __shfl_sync(0xffffffffu, i1, j);
        r0 += (c < s0) || (c == s0 && ci < i0);
        r1 += (c < s1) || (c == s1 && ci < i1);
    }
    int* dst = g_nn + (size_t)wq * KSEL;
    if (lane < KSEL) {
        if (r0 < KSEL) dst[r0] = i0;
        if (r1 < KSEL) dst[r1] = i1;
    }
}

// ================================================================
// Phase 3: warp-per-query gather-max over 30 neighbors + 13x128 conv
// ================================================================
__global__ void __launch_bounds__(256) gather_kernel(
    const float* __restrict__ W_sem, const float* __restrict__ b_sem,
    float* __restrict__ p_out)
{
    const int warp = (blockIdx.x << 3) + (threadIdx.x >> 5);
    const int lane = threadIdx.x & 31;
    const int b = warp >> 12, n = warp & (NN - 1);

    const int* nnp = g_nn + (size_t)warp * KSEL;
    int myid = nnp[lane < KSEL ? lane : 0];

    const float* base = g_fsemT + ((size_t)b * NN) * CIN + (lane << 2);
    float4 vmax = make_float4(FNINF, FNINF, FNINF, FNINF);
    #pragma unroll 6
    for (int k = 0; k < KSEL; k++) {
        int j = __shfl_sync(0xffffffffu, myid, k);
        float4 v = *(const float4*)(base + (size_t)j * CIN);
        vmax.x = fmaxf(vmax.x, v.x);
        vmax.y = fmaxf(vmax.y, v.y);
        vmax.z = fmaxf(vmax.z, v.z);
        vmax.w = fmaxf(vmax.w, v.w);
    }

    float out[SEMOUT];
    #pragma unroll
    for (int o = 0; o < SEMOUT; o++) {
        float4 w = *(const float4*)(W_sem + o * CIN + (lane << 2));
        float a = w.x * vmax.x;
        a = fmaf(w.y, vmax.y, a);
        a = fmaf(w.z, vmax.z, a);
        a = fmaf(w.w, vmax.w, a);
        a += __shfl_xor_sync(0xffffffffu, a, 16);
        a += __shfl_xor_sync(0xffffffffu, a, 8);
        a += __shfl_xor_sync(0xffffffffu, a, 4);
        a += __shfl_xor_sync(0xffffffffu, a, 2);
        a += __shfl_xor_sync(0xffffffffu, a, 1);
        out[o] = a;
    }
    if (lane == 0) {
        float* dst = p_out + ((size_t)b * SEMOUT) * NN + n;
        #pragma unroll
        for (int o = 0; o < SEMOUT; o++)
            dst[(size_t)o * NN] = out[o] + b_sem[o];
    }
}

// ================================================================
extern "C" void kernel_launch(void* const* d_in, const int* in_sizes, int n_in,
                              void* d_out, int out_size)
{
    (void)in_sizes; (void)n_in; (void)out_size;
    const float* f_sem   = (const float*)d_in[0];
    const float* f_ins   = (const float*)d_in[1];
    const float* W_adapt = (const float*)d_in[2];
    const float* b_adapt = (const float*)d_in[3];
    const float* gamma   = (const float*)d_in[4];
    const float* beta    = (const float*)d_in[5];
    const float* W_ins   = (const float*)d_in[6];
    const float* b_ins   = (const float*)d_in[7];
    const float* W_sem   = (const float*)d_in[8];
    const float* b_sem   = (const float*)d_in[9];

    float* p_out = (float*)d_out;                       // [B,13,N]
    float* e_out = p_out + (size_t)BB * SEMOUT * NN;    // [B,5,N]

    const int smem1 = (32 * WPAD + 128 * XPAD + EOUT * 128 + 8) * 4;
    cudaFuncSetAttribute(phase1_kernel, cudaFuncAttributeMaxDynamicSharedMemorySize, smem1);

    phase1_kernel<<<BB * (NN / TP), 128, smem1>>>(
        f_sem, f_ins, W_adapt, b_adapt, gamma, beta, W_ins, b_ins, e_out);
    knn_partial_kernel<<<BB * (NN / KQT) * NSLICE, KQT>>>();
    knn_merge_kernel<<<(BB * NN) / 8, 256>>>();
    gather_kernel<<<(BB * NN) / 8, 256>>>(W_sem, b_sem, p_out);
}